// round 16
// baseline (speedup 1.0000x reference)
#include <cuda_runtime.h>
#include <math.h>

#define NB 4
#define HH 2048
#define WW 2048
#define NC 3
#define TOTAL_S (NB*NC*HH*WW)          // 50331648
#define K_RANK 25165823u               // floor(0.5*(n-1)), 0-based order stat
#define H1BITS 11
#define H1SIZE (1u<<H1BITS)            // 2048
#define H2BITS 21
#define H2SIZE (1u<<H2BITS)            // 2097152
#define H2MASK (H2SIZE-1u)

// ---------------- scratch (static device globals; no allocation) -----------
__device__ float4 g_S4[TOTAL_S/4];     // S tensor, 192 MiB
__device__ unsigned g_hist1[H1SIZE];
__device__ unsigned g_hist2[H2SIZE];   // 8 MiB
__device__ unsigned g_part[1024];
__device__ unsigned g_bucket;
__device__ unsigned g_rank1;
__device__ float    g_median;

__device__ __forceinline__ unsigned mono(float f){
    unsigned u = __float_as_uint(f);
    return (u & 0x80000000u) ? ~u : (u | 0x80000000u);
}

// ---------------- K0a/b/c: zeroing split (k_harris stays 4th launch) -------
__global__ void k_zero_a(){
    unsigned i = blockIdx.x*blockDim.x + threadIdx.x;
    g_hist1[i] = 0u;
    if (i < 1024) g_part[i] = 0u;
    if (i == 0){ g_bucket = 0u; g_rank1 = 0u; g_median = 0.f; }
}
__global__ void k_zero_b(){
    unsigned i = blockIdx.x*blockDim.x + threadIdx.x;
    g_hist2[i] = 0u;
}
__global__ void k_zero_c(){
    unsigned i = blockIdx.x*blockDim.x + threadIdx.x;
    g_hist2[(H2SIZE/2) + i] = 0u;
}

// ---------------- K1: Harris S ---------------------------------------------
// Block (32,8)=256, 32x32 output tile, smem ~29.4KB, 6 blocks/SM.
// Passes: 1) x halo load  2) FUSED vertical-Sobel + products (regs)
// 3) per channel: horizontal Gaussian with 8-output strips (regs, th
// overwrites P[ch] after sync) then vertical Gaussian with 8-row strips
// (threads 0..127) + STG + hist1.
__global__ __launch_bounds__(256, 6) void k_harris(const float* __restrict__ x,
                                                   const float* __restrict__ gw){
    __shared__ float xs[40][44];        // rows gy0-4.., cols gx0-4..  (7.04KB)
    __shared__ float P[3][38][40];      // products; th[ch] overwrites P[ch] (18.24KB)
    __shared__ float gn[7];
    __shared__ unsigned hloc[H1SIZE/2]; // packed 2x16-bit counters    (4KB)

    const int tx = threadIdx.x, ty = threadIdx.y;
    const int tid = ty*32 + tx;
    const int n  = blockIdx.z;
    const int gy0 = blockIdx.y*32, gx0 = blockIdx.x*32;
    const bool edge = (blockIdx.x==0)|(blockIdx.x==63)|(blockIdx.y==0)|(blockIdx.y==63);

    for (int i = tid; i < (int)(H1SIZE/2); i += 256) hloc[i] = 0u;
    if (tid < 7){
        float s = 0.f;
        #pragma unroll
        for (int j = 0; j < 7; j++) s += gw[tid*7 + j];
        gn[tid] = s;
    }

    // ---- 1) load x halo tile: 40 rows x 10 float4 -------------------------
    const float* xn = x + (size_t)n*HH*WW;
    if (!edge){
        for (int t = tid; t < 400; t += 256){
            int r = t / 10, q = t % 10;
            const float4* rowp = reinterpret_cast<const float4*>(xn + (size_t)(gy0-4+r)*WW + (gx0-4));
            *reinterpret_cast<float4*>(&xs[r][4*q]) = rowp[q];
        }
    } else {
        for (int t = tid; t < 400; t += 256){
            int r = t / 10, q = t % 10;
            int gy = gy0 - 4 + r;
            bool rin = (unsigned)gy < HH;
            float e[4];
            #pragma unroll
            for (int k = 0; k < 4; k++){
                int gx = gx0 - 4 + 4*q + k;
                e[k] = (rin && (unsigned)gx < WW) ? xn[(size_t)gy*WW + gx] : 0.f;
            }
            *reinterpret_cast<float4*>(&xs[r][4*q]) = make_float4(e[0],e[1],e[2],e[3]);
        }
    }
    __syncthreads();

    // ---- 2) FUSED vertical Sobel + products: 38 rows x 10 strips of 4 -----
    for (int t = tid; t < 380; t += 256){
        int r = t / 10, s = t % 10;
        const float4* x0p = reinterpret_cast<const float4*>(&xs[r][4*s]);
        const float4* x1p = reinterpret_cast<const float4*>(&xs[r+1][4*s]);
        const float4* x2p = reinterpret_cast<const float4*>(&xs[r+2][4*s]);
        float4 X00 = x0p[0], X01 = x0p[1];
        float4 X10 = x1p[0], X11 = x1p[1];
        float4 X20 = x2p[0], X21 = x2p[1];
        float x0[8] = {X00.x,X00.y,X00.z,X00.w, X01.x,X01.y,X01.z,X01.w};
        float x1[8] = {X10.x,X10.y,X10.z,X10.w, X11.x,X11.y,X11.z,X11.w};
        float x2[8] = {X20.x,X20.y,X20.z,X20.w, X21.x,X21.y,X21.z,X21.w};
        float a[6], b[6];
        #pragma unroll
        for (int c = 0; c < 6; c++){
            a[c] = x0[c] + 2.f*x1[c] + x2[c];
            b[c] = x2[c] - x0[c];
        }
        float4 p0, p1, p2;
        float* p0f = &p0.x; float* p1f = &p1.x; float* p2f = &p2.x;
        bool rowin = (unsigned)(gy0 - 3 + r) < HH;
        #pragma unroll
        for (int k = 0; k < 4; k++){
            float ix = a[k+2] - a[k];
            float iy = (b[k] + b[k+2]) + 2.f*b[k+1];
            float q0 = ix*ix, q1 = iy*iy, q2 = ix*iy;
            if (edge){
                bool in = rowin && (unsigned)(gx0 - 3 + 4*s + k) < WW;
                if (!in){ q0 = 0.f; q1 = 0.f; q2 = 0.f; }
            }
            p0f[k] = q0; p1f[k] = q1; p2f[k] = q2;
        }
        *reinterpret_cast<float4*>(&P[0][r][4*s]) = p0;
        *reinterpret_cast<float4*>(&P[1][r][4*s]) = p1;
        *reinterpret_cast<float4*>(&P[2][r][4*s]) = p2;
    }
    __syncthreads();

    // ---- 3) per channel ----------------------------------------------------
    float* gS = (float*)g_S4;
    const int lane = tid & 31;
    #pragma unroll
    for (int ch = 0; ch < 3; ch++){
        float* Pch = &P[ch][0][0];      // row stride 40
        // hGauss read phase: 152 tasks (38 rows x 4 strips of 8 outputs)
        float acc[8];
        int hr = tid >> 2, hs = tid & 3;
        const bool hact = tid < 152;
        if (hact){
            const float4* p4 = reinterpret_cast<const float4*>(Pch + hr*40 + 8*hs);
            float4 q0 = p4[0], q1 = p4[1], q2 = p4[2], q3 = p4[3];
            float v[14] = {q0.x,q0.y,q0.z,q0.w, q1.x,q1.y,q1.z,q1.w,
                           q2.x,q2.y,q2.z,q2.w, q3.x,q3.y};
            #pragma unroll
            for (int k = 0; k < 8; k++){
                float sm = gn[0]*v[k];
                #pragma unroll
                for (int q = 1; q < 7; q++) sm += gn[q]*v[k+q];
                acc[k] = sm;
            }
        }
        __syncthreads();
        // write phase: th row hr, cols 8*hs..8*hs+7
        if (hact){
            float* dst = Pch + hr*40 + 8*hs;
            *reinterpret_cast<float4*>(dst)     = make_float4(acc[0],acc[1],acc[2],acc[3]);
            *reinterpret_cast<float4*>(dst + 4) = make_float4(acc[4],acc[5],acc[6],acc[7]);
        }
        __syncthreads();

        // vGauss: threads 0..127 (warps 0..3); task = col tx, 8-row strip
        if (tid < 128){
            const int r0 = (ty & 3)*8;       // ty in 0..3 here
            float v[14];
            #pragma unroll
            for (int k = 0; k < 14; k++) v[k] = Pch[(r0+k)*40 + tx];
            float* orow = gS + (((size_t)(n*NC + ch)*HH + gy0 + r0)*WW + gx0 + tx);
            #pragma unroll
            for (int k = 0; k < 8; k++){
                float sm = gn[0]*v[k];
                #pragma unroll
                for (int q = 1; q < 7; q++) sm += gn[q]*v[k+q];
                orow[(size_t)k*WW] = sm;
                unsigned bin = mono(sm) >> (32 - H1BITS);
                unsigned m = __match_any_sync(0xffffffffu, bin);
                if (lane == __ffs(m) - 1){
                    unsigned inc = (bin & 1u) ? ((unsigned)__popc(m) << 16) : (unsigned)__popc(m);
                    atomicAdd(&hloc[bin >> 1], inc);
                }
            }
        }
        __syncthreads();
    }

    for (int i = tid; i < (int)(H1SIZE/2); i += 256){
        unsigned v = hloc[i];
        if (v){
            unsigned lo = v & 0xFFFFu, hi = v >> 16;
            if (lo) atomicAdd(&g_hist1[2*i],   lo);
            if (hi) atomicAdd(&g_hist1[2*i+1], hi);
        }
    }
}

// ---------------- K2: select top-11-bit bucket -----------------------------
__global__ void k_sel1(){
    __shared__ unsigned sh[1024];
    int t = threadIdx.x;
    unsigned c0 = g_hist1[2*t], c1 = g_hist1[2*t+1];
    unsigned loc = c0 + c1;
    sh[t] = loc; __syncthreads();
    for (int st = 1; st < 1024; st <<= 1){
        unsigned v = (t >= st) ? sh[t-st] : 0u;
        __syncthreads();
        sh[t] += v;
        __syncthreads();
    }
    unsigned incl = sh[t], excl = incl - loc;
    const unsigned k = K_RANK;
    if (k >= excl && k < incl){
        if (k < excl + c0){ g_bucket = 2*t;     g_rank1 = k - excl; }
        else              { g_bucket = 2*t + 1; g_rank1 = k - excl - c0; }
    }
}

// ---------------- K3: hist2 over low-21 bits of in-bucket elements ---------
__global__ __launch_bounds__(512) void k_hist2(){
    const unsigned b = g_bucket;
    const int base = blockIdx.x*512 + threadIdx.x;
    const int stride = 1572864;
    float4 v[8];
    #pragma unroll
    for (int k = 0; k < 8; k++) v[k] = __ldcs(g_S4 + base + k*stride);
    #pragma unroll
    for (int k = 0; k < 8; k++){
        unsigned u0 = mono(v[k].x), u1 = mono(v[k].y), u2 = mono(v[k].z), u3 = mono(v[k].w);
        if ((u0 >> H2BITS) == b) atomicAdd(&g_hist2[u0 & H2MASK], 1u);
        if ((u1 >> H2BITS) == b) atomicAdd(&g_hist2[u1 & H2MASK], 1u);
        if ((u2 >> H2BITS) == b) atomicAdd(&g_hist2[u2 & H2MASK], 1u);
        if ((u3 >> H2BITS) == b) atomicAdd(&g_hist2[u3 & H2MASK], 1u);
    }
}

// ---------------- K4a: partial sums over 1024 groups of 2048 bins ----------
__global__ void k_part(){
    __shared__ unsigned red[256];
    unsigned b = blockIdx.x, t = threadIdx.x;
    unsigned s = 0;
    for (int i = t; i < 2048; i += 256) s += g_hist2[b*2048 + i];
    red[t] = s; __syncthreads();
    for (int st = 128; st > 0; st >>= 1){
        if (t < st) red[t] += red[t + st];
        __syncthreads();
    }
    if (t == 0) g_part[b] = red[0];
}

// ---------------- K4b: final select -> exact median float ------------------
__global__ void k_sel2(){
    __shared__ unsigned sh[1024];
    __shared__ unsigned sG, sR;
    int t = threadIdx.x;

    unsigned loc = g_part[t];
    sh[t] = loc; __syncthreads();
    for (int st = 1; st < 1024; st <<= 1){
        unsigned v = (t >= st) ? sh[t-st] : 0u;
        __syncthreads();
        sh[t] += v;
        __syncthreads();
    }
    unsigned incl = sh[t], excl = incl - loc;
    unsigned r1 = g_rank1;
    if (r1 >= excl && r1 < incl){ sG = t; sR = r1 - excl; }
    __syncthreads();
    unsigned G = sG, r2 = sR;

    unsigned c0 = g_hist2[G*2048 + 2*t], c1 = g_hist2[G*2048 + 2*t + 1];
    unsigned loc2 = c0 + c1;
    __syncthreads();
    sh[t] = loc2; __syncthreads();
    for (int st = 1; st < 1024; st <<= 1){
        unsigned v = (t >= st) ? sh[t-st] : 0u;
        __syncthreads();
        sh[t] += v;
        __syncthreads();
    }
    unsigned incl2 = sh[t], excl2 = incl2 - loc2;
    if (r2 >= excl2 && r2 < incl2){
        unsigned j = (r2 < excl2 + c0) ? (2*t) : (2*t + 1);
        unsigned u = (g_bucket << H2BITS) | (G*2048 + j);
        unsigned fb = (u & 0x80000000u) ? (u ^ 0x80000000u) : ~u;
        g_median = __uint_as_float(fb);
    }
}

// ---------------- K5: threshold + separable 7x7 NMS, 64x64 tiles -----------
__global__ __launch_bounds__(512) void k_nms(float* __restrict__ out){
    __shared__ float xt[70][76];        // rows gy0-3.., cols gx0-4.. (c=0..71)
    __shared__ float rm[70][68];        // row max, j=0..63
    const float med = g_median;
    const int nc  = blockIdx.z;
    const int gy0 = blockIdx.y*64, gx0 = blockIdx.x*64;
    const float* Sp = (const float*)g_S4 + (size_t)nc*HH*WW;
    const int tid = threadIdx.y*32 + threadIdx.x;
    const bool xin = (gx0 >= 4) && (gx0 + 68 <= WW);

    for (int t = tid; t < 70*18; t += 512){
        int r = t / 18, q = t % 18;
        int gy = gy0 - 3 + r;
        float4 o;
        if ((unsigned)gy < HH){
            const float* rowp = Sp + (size_t)gy*WW + (gx0 - 4);
            if (xin){
                float4 v = __ldcs(reinterpret_cast<const float4*>(rowp) + q);
                o.x = (v.x > med) ? v.x : 0.f;
                o.y = (v.y > med) ? v.y : 0.f;
                o.z = (v.z > med) ? v.z : 0.f;
                o.w = (v.w > med) ? v.w : 0.f;
            } else {
                float e[4];
                #pragma unroll
                for (int k = 0; k < 4; k++){
                    int gx = gx0 - 4 + 4*q + k;
                    float v = -INFINITY;
                    if ((unsigned)gx < WW){
                        float s = rowp[4*q + k];
                        v = (s > med) ? s : 0.f;
                    }
                    e[k] = v;
                }
                o = make_float4(e[0],e[1],e[2],e[3]);
            }
        } else {
            o = make_float4(-INFINITY,-INFINITY,-INFINITY,-INFINITY);
        }
        *reinterpret_cast<float4*>(&xt[r][4*q]) = o;
    }
    __syncthreads();

    for (int t = tid; t < 70*16; t += 512){
        int r = t >> 4, s = t & 15;
        const float4* p4 = reinterpret_cast<const float4*>(&xt[r][4*s]);
        float4 q0 = p4[0], q1 = p4[1], q2 = p4[2];
        float v[12] = {q0.x,q0.y,q0.z,q0.w, q1.x,q1.y,q1.z,q1.w, q2.x,q2.y,q2.z,q2.w};
        float o[4];
        #pragma unroll
        for (int k = 0; k < 4; k++){
            float m = v[k+1];
            #pragma unroll
            for (int q = 2; q < 8; q++) m = fmaxf(m, v[k+q]);
            o[k] = m;
        }
        *reinterpret_cast<float4*>(&rm[r][4*s]) = make_float4(o[0],o[1],o[2],o[3]);
    }
    __syncthreads();

    float* op = out + (size_t)nc*HH*WW;
    for (int t = tid; t < 64*16; t += 512){
        int ii = t >> 4, s = t & 15;
        float4 m4 = *reinterpret_cast<const float4*>(&rm[ii][4*s]);
        #pragma unroll
        for (int q = 1; q < 7; q++){
            float4 v = *reinterpret_cast<const float4*>(&rm[ii+q][4*s]);
            m4.x = fmaxf(m4.x, v.x); m4.y = fmaxf(m4.y, v.y);
            m4.z = fmaxf(m4.z, v.z); m4.w = fmaxf(m4.w, v.w);
        }
        float4 xc = *reinterpret_cast<const float4*>(&xt[ii+3][4*s+4]);
        float4 o;
        o.x = (xc.x == m4.x) ? xc.x : 0.f;
        o.y = (xc.y == m4.y) ? xc.y : 0.f;
        o.z = (xc.z == m4.z) ? xc.z : 0.f;
        o.w = (xc.w == m4.w) ? xc.w : 0.f;
        *reinterpret_cast<float4*>(op + (size_t)(gy0 + ii)*WW + gx0 + 4*s) = o;
    }
}

// ---------------- launcher --------------------------------------------------
extern "C" void kernel_launch(void* const* d_in, const int* in_sizes, int n_in,
                              void* d_out, int out_size){
    const float* x    = (const float*)d_in[0];   // (4,1,2048,2048)
    const float* gw   = (const float*)d_in[2];   // (3,1,7,7)
    float* out = (float*)d_out;

    k_zero_a<<<2, 1024>>>();
    k_zero_b<<<1024, 1024>>>();
    k_zero_c<<<1024, 1024>>>();
    dim3 g1(WW/32, HH/32, NB);
    k_harris<<<g1, dim3(32,8)>>>(x, gw);         // 4th launch -> profiled
    k_sel1<<<1, 1024>>>();
    k_hist2<<<3072, 512>>>();
    k_part<<<1024, 256>>>();
    k_sel2<<<1, 1024>>>();
    dim3 g5(WW/64, HH/64, NB*NC);
    k_nms<<<g5, dim3(32,16)>>>(out);
}

// round 17
// speedup vs baseline: 1.0792x; 1.0792x over previous
#include <cuda_runtime.h>
#include <math.h>

#define NB 4
#define HH 2048
#define WW 2048
#define NC 3
#define TOTAL_S (NB*NC*HH*WW)          // 50331648
#define K_RANK 25165823u               // floor(0.5*(n-1)), 0-based order stat
#define H1BITS 11
#define H1SIZE (1u<<H1BITS)            // 2048
#define H2BITS 21
#define H2SIZE (1u<<H2BITS)            // 2097152
#define H2MASK (H2SIZE-1u)

// ---------------- scratch (static device globals; no allocation) -----------
__device__ float4 g_S4[TOTAL_S/4];     // S tensor, 192 MiB
__device__ unsigned g_hist1[H1SIZE];
__device__ unsigned g_hist2[H2SIZE];   // 8 MiB
__device__ unsigned g_part[1024];
__device__ unsigned g_bucket;
__device__ unsigned g_rank1;
__device__ float    g_median;

__device__ __forceinline__ unsigned mono(float f){
    unsigned u = __float_as_uint(f);
    return (u & 0x80000000u) ? ~u : (u | 0x80000000u);
}

// ---------------- K0a/b/c: zeroing split (k_harris stays 4th launch) -------
__global__ void k_zero_a(){
    unsigned i = blockIdx.x*blockDim.x + threadIdx.x;   // 2048 threads
    g_hist1[i] = 0u;
    if (i < 1024) g_part[i] = 0u;
    if (i == 0){ g_bucket = 0u; g_rank1 = 0u; g_median = 0.f; }
}
__global__ void k_zero_b(){                             // first 4 MiB, uint4
    unsigned i = blockIdx.x*blockDim.x + threadIdx.x;   // 2^18 threads
    reinterpret_cast<uint4*>(g_hist2)[i] = make_uint4(0u,0u,0u,0u);
}
__global__ void k_zero_c(){                             // second 4 MiB, uint4
    unsigned i = blockIdx.x*blockDim.x + threadIdx.x;
    reinterpret_cast<uint4*>(g_hist2)[(H2SIZE/8) + i] = make_uint4(0u,0u,0u,0u);
}

// ---------------- K1: Harris S (R15 config — best measured: 169us) ---------
// Block (32,8)=256, 32x32 output tile, smem ~29.4KB, 6 blocks/SM.
__global__ __launch_bounds__(256, 6) void k_harris(const float* __restrict__ x,
                                                   const float* __restrict__ gw){
    __shared__ float xs[40][44];        // rows gy0-4.., cols gx0-4..  (7.04KB)
    __shared__ float P[3][38][40];      // products; th[ch] overwrites P[ch] (18.24KB)
    __shared__ float gn[7];
    __shared__ unsigned hloc[H1SIZE/2]; // packed 2x16-bit counters    (4KB)

    const int tx = threadIdx.x, ty = threadIdx.y;
    const int tid = ty*32 + tx;
    const int n  = blockIdx.z;
    const int gy0 = blockIdx.y*32, gx0 = blockIdx.x*32;
    const bool edge = (blockIdx.x==0)|(blockIdx.x==63)|(blockIdx.y==0)|(blockIdx.y==63);

    for (int i = tid; i < (int)(H1SIZE/2); i += 256) hloc[i] = 0u;
    if (tid < 7){
        float s = 0.f;
        #pragma unroll
        for (int j = 0; j < 7; j++) s += gw[tid*7 + j];
        gn[tid] = s;
    }

    // ---- 1) load x halo tile: 40 rows x 10 float4 -------------------------
    const float* xn = x + (size_t)n*HH*WW;
    if (!edge){
        for (int t = tid; t < 400; t += 256){
            int r = t / 10, q = t % 10;
            const float4* rowp = reinterpret_cast<const float4*>(xn + (size_t)(gy0-4+r)*WW + (gx0-4));
            *reinterpret_cast<float4*>(&xs[r][4*q]) = rowp[q];
        }
    } else {
        for (int t = tid; t < 400; t += 256){
            int r = t / 10, q = t % 10;
            int gy = gy0 - 4 + r;
            bool rin = (unsigned)gy < HH;
            float e[4];
            #pragma unroll
            for (int k = 0; k < 4; k++){
                int gx = gx0 - 4 + 4*q + k;
                e[k] = (rin && (unsigned)gx < WW) ? xn[(size_t)gy*WW + gx] : 0.f;
            }
            *reinterpret_cast<float4*>(&xs[r][4*q]) = make_float4(e[0],e[1],e[2],e[3]);
        }
    }
    __syncthreads();

    // ---- 2) FUSED vertical Sobel + products: 38 rows x 10 strips of 4 -----
    for (int t = tid; t < 380; t += 256){
        int r = t / 10, s = t % 10;
        const float4* x0p = reinterpret_cast<const float4*>(&xs[r][4*s]);
        const float4* x1p = reinterpret_cast<const float4*>(&xs[r+1][4*s]);
        const float4* x2p = reinterpret_cast<const float4*>(&xs[r+2][4*s]);
        float4 X00 = x0p[0], X01 = x0p[1];
        float4 X10 = x1p[0], X11 = x1p[1];
        float4 X20 = x2p[0], X21 = x2p[1];
        float x0[8] = {X00.x,X00.y,X00.z,X00.w, X01.x,X01.y,X01.z,X01.w};
        float x1[8] = {X10.x,X10.y,X10.z,X10.w, X11.x,X11.y,X11.z,X11.w};
        float x2[8] = {X20.x,X20.y,X20.z,X20.w, X21.x,X21.y,X21.z,X21.w};
        float a[6], b[6];
        #pragma unroll
        for (int c = 0; c < 6; c++){
            a[c] = x0[c] + 2.f*x1[c] + x2[c];
            b[c] = x2[c] - x0[c];
        }
        float4 p0, p1, p2;
        float* p0f = &p0.x; float* p1f = &p1.x; float* p2f = &p2.x;
        bool rowin = (unsigned)(gy0 - 3 + r) < HH;
        #pragma unroll
        for (int k = 0; k < 4; k++){
            float ix = a[k+2] - a[k];
            float iy = (b[k] + b[k+2]) + 2.f*b[k+1];
            float q0 = ix*ix, q1 = iy*iy, q2 = ix*iy;
            if (edge){
                bool in = rowin && (unsigned)(gx0 - 3 + 4*s + k) < WW;
                if (!in){ q0 = 0.f; q1 = 0.f; q2 = 0.f; }
            }
            p0f[k] = q0; p1f[k] = q1; p2f[k] = q2;
        }
        *reinterpret_cast<float4*>(&P[0][r][4*s]) = p0;
        *reinterpret_cast<float4*>(&P[1][r][4*s]) = p1;
        *reinterpret_cast<float4*>(&P[2][r][4*s]) = p2;
    }
    __syncthreads();

    // ---- 3) per channel: hGauss (regs, th overwrites P[ch]), vGauss -------
    float* gS = (float*)g_S4;
    const int lane = tid & 31;
    const int r0 = ty*4;
    #pragma unroll
    for (int ch = 0; ch < 3; ch++){
        float* Pch = &P[ch][0][0];      // row stride 40
        float o1[4], o2[4];
        {
            int t = tid;                 // < 304 always
            int r = t >> 3, s = t & 7;
            const float4* p4 = reinterpret_cast<const float4*>(Pch + r*40 + 4*s);
            float4 q0 = p4[0], q1 = p4[1], q2 = p4[2];
            float v[12] = {q0.x,q0.y,q0.z,q0.w, q1.x,q1.y,q1.z,q1.w, q2.x,q2.y,q2.z,q2.w};
            #pragma unroll
            for (int k = 0; k < 4; k++){
                float sm = gn[0]*v[k];
                #pragma unroll
                for (int q = 1; q < 7; q++) sm += gn[q]*v[k+q];
                o1[k] = sm;
            }
        }
        const bool has2 = (tid + 256) < 304;
        if (has2){
            int t = tid + 256;
            int r = t >> 3, s = t & 7;
            const float4* p4 = reinterpret_cast<const float4*>(Pch + r*40 + 4*s);
            float4 q0 = p4[0], q1 = p4[1], q2 = p4[2];
            float v[12] = {q0.x,q0.y,q0.z,q0.w, q1.x,q1.y,q1.z,q1.w, q2.x,q2.y,q2.z,q2.w};
            #pragma unroll
            for (int k = 0; k < 4; k++){
                float sm = gn[0]*v[k];
                #pragma unroll
                for (int q = 1; q < 7; q++) sm += gn[q]*v[k+q];
                o2[k] = sm;
            }
        }
        __syncthreads();
        {
            int r = tid >> 3, s = tid & 7;
            *reinterpret_cast<float4*>(Pch + r*40 + 4*s) = make_float4(o1[0],o1[1],o1[2],o1[3]);
        }
        if (has2){
            int t = tid + 256;
            int r = t >> 3, s = t & 7;
            *reinterpret_cast<float4*>(Pch + r*40 + 4*s) = make_float4(o2[0],o2[1],o2[2],o2[3]);
        }
        __syncthreads();

        // vertical Gaussian + store S + hist1 (one task per thread)
        {
            float v[10];
            #pragma unroll
            for (int k = 0; k < 10; k++) v[k] = Pch[(r0+k)*40 + tx];
            float* orow = gS + (((size_t)(n*NC + ch)*HH + gy0 + r0)*WW + gx0 + tx);
            #pragma unroll
            for (int k = 0; k < 4; k++){
                float sm = gn[0]*v[k];
                #pragma unroll
                for (int q = 1; q < 7; q++) sm += gn[q]*v[k+q];
                orow[(size_t)k*WW] = sm;
                unsigned bin = mono(sm) >> (32 - H1BITS);
                unsigned m = __match_any_sync(0xffffffffu, bin);
                if (lane == __ffs(m) - 1){
                    unsigned inc = (bin & 1u) ? ((unsigned)__popc(m) << 16) : (unsigned)__popc(m);
                    atomicAdd(&hloc[bin >> 1], inc);
                }
            }
        }
        __syncthreads();
    }

    for (int i = tid; i < (int)(H1SIZE/2); i += 256){
        unsigned v = hloc[i];
        if (v){
            unsigned lo = v & 0xFFFFu, hi = v >> 16;
            if (lo) atomicAdd(&g_hist1[2*i],   lo);
            if (hi) atomicAdd(&g_hist1[2*i+1], hi);
        }
    }
}

// ---------------- K2: select top-11-bit bucket -----------------------------
__global__ void k_sel1(){
    __shared__ unsigned sh[1024];
    int t = threadIdx.x;
    unsigned c0 = g_hist1[2*t], c1 = g_hist1[2*t+1];
    unsigned loc = c0 + c1;
    sh[t] = loc; __syncthreads();
    for (int st = 1; st < 1024; st <<= 1){
        unsigned v = (t >= st) ? sh[t-st] : 0u;
        __syncthreads();
        sh[t] += v;
        __syncthreads();
    }
    unsigned incl = sh[t], excl = incl - loc;
    const unsigned k = K_RANK;
    if (k >= excl && k < incl){
        if (k < excl + c0){ g_bucket = 2*t;     g_rank1 = k - excl; }
        else              { g_bucket = 2*t + 1; g_rank1 = k - excl - c0; }
    }
}

// ---------------- K3: hist2 over low-21 bits of in-bucket elements ---------
__global__ __launch_bounds__(512) void k_hist2(){
    const unsigned b = g_bucket;
    const int base = blockIdx.x*512 + threadIdx.x;
    const int stride = 1572864;
    float4 v[8];
    #pragma unroll
    for (int k = 0; k < 8; k++) v[k] = __ldcs(g_S4 + base + k*stride);
    #pragma unroll
    for (int k = 0; k < 8; k++){
        unsigned u0 = mono(v[k].x), u1 = mono(v[k].y), u2 = mono(v[k].z), u3 = mono(v[k].w);
        if ((u0 >> H2BITS) == b) atomicAdd(&g_hist2[u0 & H2MASK], 1u);
        if ((u1 >> H2BITS) == b) atomicAdd(&g_hist2[u1 & H2MASK], 1u);
        if ((u2 >> H2BITS) == b) atomicAdd(&g_hist2[u2 & H2MASK], 1u);
        if ((u3 >> H2BITS) == b) atomicAdd(&g_hist2[u3 & H2MASK], 1u);
    }
}

// ---------------- K4a: partial sums over 1024 groups of 2048 bins ----------
__global__ __launch_bounds__(256) void k_part(){
    __shared__ unsigned red[256];
    unsigned b = blockIdx.x, t = threadIdx.x;
    const uint4* hp = reinterpret_cast<const uint4*>(g_hist2 + b*2048);
    unsigned s = 0;
    #pragma unroll
    for (int i = 0; i < 2; i++){
        uint4 v = hp[t + i*256];
        s += v.x + v.y + v.z + v.w;
    }
    red[t] = s; __syncthreads();
    for (int st = 128; st > 0; st >>= 1){
        if (t < st) red[t] += red[t + st];
        __syncthreads();
    }
    if (t == 0) g_part[b] = red[0];
}

// ---------------- K4b: final select -> exact median float ------------------
__global__ void k_sel2(){
    __shared__ unsigned sh[1024];
    __shared__ unsigned sG, sR;
    int t = threadIdx.x;

    unsigned loc = g_part[t];
    sh[t] = loc; __syncthreads();
    for (int st = 1; st < 1024; st <<= 1){
        unsigned v = (t >= st) ? sh[t-st] : 0u;
        __syncthreads();
        sh[t] += v;
        __syncthreads();
    }
    unsigned incl = sh[t], excl = incl - loc;
    unsigned r1 = g_rank1;
    if (r1 >= excl && r1 < incl){ sG = t; sR = r1 - excl; }
    __syncthreads();
    unsigned G = sG, r2 = sR;

    unsigned c0 = g_hist2[G*2048 + 2*t], c1 = g_hist2[G*2048 + 2*t + 1];
    unsigned loc2 = c0 + c1;
    __syncthreads();
    sh[t] = loc2; __syncthreads();
    for (int st = 1; st < 1024; st <<= 1){
        unsigned v = (t >= st) ? sh[t-st] : 0u;
        __syncthreads();
        sh[t] += v;
        __syncthreads();
    }
    unsigned incl2 = sh[t], excl2 = incl2 - loc2;
    if (r2 >= excl2 && r2 < incl2){
        unsigned j = (r2 < excl2 + c0) ? (2*t) : (2*t + 1);
        unsigned u = (g_bucket << H2BITS) | (G*2048 + j);
        unsigned fb = (u & 0x80000000u) ? (u ^ 0x80000000u) : ~u;
        g_median = __uint_as_float(fb);
    }
}

// ---------------- K5: threshold + separable 7x7 NMS, 64x64 tiles -----------
__global__ __launch_bounds__(512) void k_nms(float* __restrict__ out){
    __shared__ float xt[70][76];        // rows gy0-3.., cols gx0-4.. (c=0..71)
    __shared__ float rm[70][68];        // row max, j=0..63
    const float med = g_median;
    const int nc  = blockIdx.z;
    const int gy0 = blockIdx.y*64, gx0 = blockIdx.x*64;
    const float* Sp = (const float*)g_S4 + (size_t)nc*HH*WW;
    const int tid = threadIdx.y*32 + threadIdx.x;
    const bool xin = (gx0 >= 4) && (gx0 + 68 <= WW);

    for (int t = tid; t < 70*18; t += 512){
        int r = t / 18, q = t % 18;
        int gy = gy0 - 3 + r;
        float4 o;
        if ((unsigned)gy < HH){
            const float* rowp = Sp + (size_t)gy*WW + (gx0 - 4);
            if (xin){
                float4 v = __ldcs(reinterpret_cast<const float4*>(rowp) + q);
                o.x = (v.x > med) ? v.x : 0.f;
                o.y = (v.y > med) ? v.y : 0.f;
                o.z = (v.z > med) ? v.z : 0.f;
                o.w = (v.w > med) ? v.w : 0.f;
            } else {
                float e[4];
                #pragma unroll
                for (int k = 0; k < 4; k++){
                    int gx = gx0 - 4 + 4*q + k;
                    float v = -INFINITY;
                    if ((unsigned)gx < WW){
                        float s = rowp[4*q + k];
                        v = (s > med) ? s : 0.f;
                    }
                    e[k] = v;
                }
                o = make_float4(e[0],e[1],e[2],e[3]);
            }
        } else {
            o = make_float4(-INFINITY,-INFINITY,-INFINITY,-INFINITY);
        }
        *reinterpret_cast<float4*>(&xt[r][4*q]) = o;
    }
    __syncthreads();

    for (int t = tid; t < 70*16; t += 512){
        int r = t >> 4, s = t & 15;
        const float4* p4 = reinterpret_cast<const float4*>(&xt[r][4*s]);
        float4 q0 = p4[0], q1 = p4[1], q2 = p4[2];
        float v[12] = {q0.x,q0.y,q0.z,q0.w, q1.x,q1.y,q1.z,q1.w, q2.x,q2.y,q2.z,q2.w};
        float o[4];
        #pragma unroll
        for (int k = 0; k < 4; k++){
            float m = v[k+1];
            #pragma unroll
            for (int q = 2; q < 8; q++) m = fmaxf(m, v[k+q]);
            o[k] = m;
        }
        *reinterpret_cast<float4*>(&rm[r][4*s]) = make_float4(o[0],o[1],o[2],o[3]);
    }
    __syncthreads();

    float* op = out + (size_t)nc*HH*WW;
    for (int t = tid; t < 64*16; t += 512){
        int ii = t >> 4, s = t & 15;
        float4 m4 = *reinterpret_cast<const float4*>(&rm[ii][4*s]);
        #pragma unroll
        for (int q = 1; q < 7; q++){
            float4 v = *reinterpret_cast<const float4*>(&rm[ii+q][4*s]);
            m4.x = fmaxf(m4.x, v.x); m4.y = fmaxf(m4.y, v.y);
            m4.z = fmaxf(m4.z, v.z); m4.w = fmaxf(m4.w, v.w);
        }
        float4 xc = *reinterpret_cast<const float4*>(&xt[ii+3][4*s+4]);
        float4 o;
        o.x = (xc.x == m4.x) ? xc.x : 0.f;
        o.y = (xc.y == m4.y) ? xc.y : 0.f;
        o.z = (xc.z == m4.z) ? xc.z : 0.f;
        o.w = (xc.w == m4.w) ? xc.w : 0.f;
        *reinterpret_cast<float4*>(op + (size_t)(gy0 + ii)*WW + gx0 + 4*s) = o;
    }
}

// ---------------- launcher --------------------------------------------------
extern "C" void kernel_launch(void* const* d_in, const int* in_sizes, int n_in,
                              void* d_out, int out_size){
    const float* x    = (const float*)d_in[0];   // (4,1,2048,2048)
    const float* gw   = (const float*)d_in[2];   // (3,1,7,7)
    float* out = (float*)d_out;

    k_zero_a<<<2, 1024>>>();
    k_zero_b<<<512, 512>>>();                    // 2^18 threads x uint4
    k_zero_c<<<512, 512>>>();
    dim3 g1(WW/32, HH/32, NB);
    k_harris<<<g1, dim3(32,8)>>>(x, gw);         // 4th launch -> profiled
    k_sel1<<<1, 1024>>>();
    k_hist2<<<3072, 512>>>();
    k_part<<<1024, 256>>>();
    k_sel2<<<1, 1024>>>();
    dim3 g5(WW/64, HH/64, NB*NC);
    k_nms<<<g5, dim3(32,16)>>>(out);
}